// round 7
// baseline (speedup 1.0000x reference)
#include <cuda_runtime.h>
#include <cuda_bf16.h>
#include <math.h>
#include <stdint.h>

#define BB   32
#define LL   1024
#define DIN  2048
#define HH   1024
#define NLB  21
#define EE   768
#define MM   (BB*LL)
#define LN_EPS 1e-5f

// ---------------- device scratch ----------------
__device__ __align__(16) float g_h[(size_t)MM * HH];
__device__ __align__(16) __nv_bfloat16 g_ahi[(size_t)MM * DIN];
__device__ __align__(16) __nv_bfloat16 g_alo[(size_t)MM * DIN];
__device__ __align__(16) __nv_bfloat16 g_bhi[(size_t)HH * DIN];   // [n][k]
__device__ __align__(16) __nv_bfloat16 g_blo[(size_t)HH * DIN];
__device__ float g_labelh[NLB * HH];
__device__ float g_rowmax[MM];
__device__ float g_nll[BB];

// ---------------- helpers ----------------
__device__ __forceinline__ uint32_t smem_u32(const void* p) {
    uint32_t a;
    asm("{ .reg .u64 t; cvta.to.shared.u64 t, %1; cvt.u32.u64 %0, t; }" : "=r"(a) : "l"(p));
    return a;
}
#define CP16(ds, sp) asm volatile("cp.async.cg.shared.global [%0], [%1], 16;" \
    :: "r"(ds), "l"(__cvta_generic_to_global(sp)) : "memory")
#define CP_COMMIT() asm volatile("cp.async.commit_group;" ::: "memory")
#define LDSM_X4(r0, r1, r2, r3, a) asm volatile( \
    "ldmatrix.sync.aligned.m8n8.x4.shared.b16 {%0,%1,%2,%3}, [%4];" \
    : "=r"(r0), "=r"(r1), "=r"(r2), "=r"(r3) : "r"(a))
#define MMA4(d, a0, a1, a2, a3, b0, b1) asm volatile( \
    "mma.sync.aligned.m16n8k16.row.col.f32.bf16.bf16.f32 " \
    "{%0,%1,%2,%3}, {%4,%5,%6,%7}, {%8,%9}, {%0,%1,%2,%3};" \
    : "+f"((d)[0]), "+f"((d)[1]), "+f"((d)[2]), "+f"((d)[3]) \
    : "r"(a0), "r"(a1), "r"(a2), "r"(a3), "r"(b0), "r"(b1))

// ---------------- split kernels ----------------
__global__ void ksplitA(const float* __restrict__ X) {
    size_t i = ((size_t)blockIdx.x * blockDim.x + threadIdx.x) * 4;
    float4 v = *(const float4*)(X + i);
    __nv_bfloat16 h0 = __float2bfloat16(v.x), h1 = __float2bfloat16(v.y);
    __nv_bfloat16 h2 = __float2bfloat16(v.z), h3 = __float2bfloat16(v.w);
    __nv_bfloat16 l0 = __float2bfloat16(v.x - __bfloat162float(h0));
    __nv_bfloat16 l1 = __float2bfloat16(v.y - __bfloat162float(h1));
    __nv_bfloat16 l2 = __float2bfloat16(v.z - __bfloat162float(h2));
    __nv_bfloat16 l3 = __float2bfloat16(v.w - __bfloat162float(h3));
    *(__nv_bfloat162*)(g_ahi + i)     = __nv_bfloat162(h0, h1);
    *(__nv_bfloat162*)(g_ahi + i + 2) = __nv_bfloat162(h2, h3);
    *(__nv_bfloat162*)(g_alo + i)     = __nv_bfloat162(l0, l1);
    *(__nv_bfloat162*)(g_alo + i + 2) = __nv_bfloat162(l2, l3);
}

__global__ void ksplitB(const float* __restrict__ W) {
    __shared__ float tile[32][33];
    const int kb = blockIdx.x * 32, nb = blockIdx.y * 32;
    const int tx = threadIdx.x, ty = threadIdx.y;  // 32 x 8
    #pragma unroll
    for (int i = 0; i < 32; i += 8)
        tile[ty + i][tx] = W[(size_t)(kb + ty + i) * HH + nb + tx];
    __syncthreads();
    #pragma unroll
    for (int i = 0; i < 32; i += 8) {
        float v = tile[tx][ty + i];   // W[kb+tx][nb+ty+i]
        __nv_bfloat16 hi = __float2bfloat16(v);
        __nv_bfloat16 lo = __float2bfloat16(v - __bfloat162float(hi));
        size_t o = (size_t)(nb + ty + i) * DIN + kb + tx;
        g_bhi[o] = hi; g_blo[o] = lo;
    }
}

// ---------------- K0: label_h ----------------
__global__ void k0_labelh(const float* __restrict__ lt, const float* __restrict__ wl) {
    const int n = blockIdx.y;
    const int h = blockIdx.x * 128 + threadIdx.x;
    float acc = 0.f;
    const float* ltr = lt + n * EE;
    #pragma unroll 4
    for (int e = 0; e < EE; e++) acc = fmaf(ltr[e], wl[(size_t)e * HH + h], acc);
    g_labelh[n * HH + h] = acc;
}

// ---------------- K1: bf16-split GEMM via mma.sync, 128x256 tile, 512 thr, 3-stage ----------------
#define KC2 32
#define NCH2 (DIN / KC2)       // 64
#define TPITCH 80              // smem row pitch bytes
#define TILEA (128 * TPITCH)   // 10240
#define TILEB2 (256 * TPITCH)  // 20480
#define STAGEB (2 * TILEA + 2 * TILEB2)  // 61440
#define NSTAGE 3

__device__ __forceinline__ void prefetch_chunk(uint32_t sbuf, int cRow, int cCol,
                                               int k0, int tid) {
    #pragma unroll
    for (int q = 0; q < 6; q++) {
        const int id = q * 512 + tid;
        const int c4 = id & 3;
        if (id < 1024) {             // A tiles: 128 rows x 4 xfers, hi then lo
            const int r = (id >> 2) & 127;
            const bool hi = id < 512;
            const __nv_bfloat16* src = hi ? g_ahi : g_alo;
            const uint32_t dof = sbuf + (hi ? 0u : (uint32_t)TILEA)
                               + (uint32_t)(r * TPITCH + c4 * 16);
            CP16(dof, src + (size_t)(cRow + r) * DIN + k0 + c4 * 8);
        } else {                     // B tiles: 256 rows x 4 xfers, hi then lo
            const int r = (id >> 2) & 255;
            const bool hi = id < 2048;
            const __nv_bfloat16* src = hi ? g_bhi : g_blo;
            const uint32_t dof = sbuf + 2u * TILEA + (hi ? 0u : (uint32_t)TILEB2)
                               + (uint32_t)(r * TPITCH + c4 * 16);
            CP16(dof, src + (size_t)(cCol + r) * DIN + k0 + c4 * 8);
        }
    }
}

__global__ __launch_bounds__(512, 1) void k1_mma() {
    extern __shared__ char sm[];
    const int tid = threadIdx.x, lane = tid & 31, wid = tid >> 5;
    const int cCol = blockIdx.x * 256, cRow = blockIdx.y * 128;
    const int wm = wid >> 2, wn = wid & 3;  // warp tile 32M x 64N
    const uint32_t sb = smem_u32(sm);

    float acc[2][8][4];
    #pragma unroll
    for (int i = 0; i < 2; i++)
        #pragma unroll
        for (int j = 0; j < 8; j++)
            #pragma unroll
            for (int k = 0; k < 4; k++) acc[i][j][k] = 0.f;

    prefetch_chunk(sb, cRow, cCol, 0, tid);
    CP_COMMIT();
    prefetch_chunk(sb + STAGEB, cRow, cCol, KC2, tid);
    CP_COMMIT();

    const int aRow = wm * 32 + (lane & 15);            // + mt*16
    const uint32_t aKb = (uint32_t)((lane >> 4) * 16); // + ks*32
    const int bRow = wn * 64 + ((lane >> 4) & 1) * 8 + (lane & 7); // + p*16
    const uint32_t bKb = (uint32_t)(((lane >> 3) & 1) * 16);

    int stage = 0;
    for (int c = 0; c < NCH2; c++) {
        if (c + 1 < NCH2) {
            asm volatile("cp.async.wait_group 1;" ::: "memory");
        } else {
            asm volatile("cp.async.wait_group 0;" ::: "memory");
        }
        __syncthreads();
        // prefetch chunk c+2 into the stage chunk c-1 used (all warps are past it)
        if (c + 2 < NCH2) {
            int ps = stage + 2; if (ps >= NSTAGE) ps -= NSTAGE;
            prefetch_chunk(sb + (uint32_t)(ps * STAGEB), cRow, cCol, (c + 2) * KC2, tid);
            CP_COMMIT();
        }
        const uint32_t st = sb + (uint32_t)(stage * STAGEB);

        #pragma unroll
        for (int ks = 0; ks < 2; ks++) {
            uint32_t ah[2][4], al[2][4];
            #pragma unroll
            for (int mt = 0; mt < 2; mt++) {
                const uint32_t ao = st + (uint32_t)((aRow + mt * 16) * TPITCH) + aKb + (uint32_t)(ks * 32);
                LDSM_X4(ah[mt][0], ah[mt][1], ah[mt][2], ah[mt][3], ao);
                LDSM_X4(al[mt][0], al[mt][1], al[mt][2], al[mt][3], ao + TILEA);
            }
            #pragma unroll
            for (int p = 0; p < 4; p++) {
                const uint32_t bo = st + 2u * TILEA +
                    (uint32_t)((bRow + p * 16) * TPITCH) + bKb + (uint32_t)(ks * 32);
                uint32_t bh0, bh1, bh2, bh3, bl0, bl1, bl2, bl3;
                LDSM_X4(bh0, bh1, bh2, bh3, bo);
                LDSM_X4(bl0, bl1, bl2, bl3, bo + TILEB2);
                #pragma unroll
                for (int mt = 0; mt < 2; mt++) {
                    MMA4(acc[mt][2*p],   ah[mt][0], ah[mt][1], ah[mt][2], ah[mt][3], bh0, bh1);
                    MMA4(acc[mt][2*p],   ah[mt][0], ah[mt][1], ah[mt][2], ah[mt][3], bl0, bl1);
                    MMA4(acc[mt][2*p],   al[mt][0], al[mt][1], al[mt][2], al[mt][3], bh0, bh1);
                    MMA4(acc[mt][2*p+1], ah[mt][0], ah[mt][1], ah[mt][2], ah[mt][3], bh2, bh3);
                    MMA4(acc[mt][2*p+1], ah[mt][0], ah[mt][1], ah[mt][2], ah[mt][3], bl2, bl3);
                    MMA4(acc[mt][2*p+1], al[mt][0], al[mt][1], al[mt][2], al[mt][3], bh2, bh3);
                }
            }
        }
        stage = (stage + 1 == NSTAGE) ? 0 : stage + 1;
    }

    #pragma unroll
    for (int mt = 0; mt < 2; mt++)
        #pragma unroll
        for (int nt = 0; nt < 8; nt++) {
            const int row = cRow + wm * 32 + mt * 16 + (lane >> 2);
            const int col = cCol + wn * 64 + nt * 8 + (lane & 3) * 2;
            float2 v0 = make_float2(acc[mt][nt][0], acc[mt][nt][1]);
            float2 v1 = make_float2(acc[mt][nt][2], acc[mt][nt][3]);
            *(float2*)&g_h[(size_t)row * HH + col] = v0;
            *(float2*)&g_h[(size_t)(row + 8) * HH + col] = v1;
        }
}

// ---------------- K2: LN + exact GELU + logits ----------------
#define RPB 16
__global__ __launch_bounds__(256)
void k2_ln_gelu_logits(const float* __restrict__ gamma, const float* __restrict__ beta,
                       const float* __restrict__ temp_p, float* __restrict__ logits) {
    extern __shared__ float smem[];
    float* slh = smem;
    float* sth = smem + NLB * HH;
    float* red = sth + HH;
    const int t = threadIdx.x, lane = t & 31, wid = t >> 5;

    for (int i = t; i < NLB * HH; i += 256) slh[i] = g_labelh[i];
    const float tempv = *temp_p;
    const float4 g4 = *(const float4*)&gamma[t * 4];
    const float4 b4 = *(const float4*)&beta[t * 4];
    __syncthreads();

    const int row0 = blockIdx.x * RPB;
    for (int r = 0; r < RPB; r++) {
        const int row = row0 + r;
        const float4 xv = *(const float4*)&g_h[(size_t)row * HH + t * 4];
        float s = xv.x + xv.y + xv.z + xv.w;
        float q = xv.x*xv.x + xv.y*xv.y + xv.z*xv.z + xv.w*xv.w;
        #pragma unroll
        for (int o = 16; o > 0; o >>= 1) {
            s += __shfl_xor_sync(0xffffffffu, s, o);
            q += __shfl_xor_sync(0xffffffffu, q, o);
        }
        if (lane == 0) { red[wid] = s; red[8 + wid] = q; }
        __syncthreads();
        float S = 0.f, Q = 0.f;
        #pragma unroll
        for (int w = 0; w < 8; w++) { S += red[w]; Q += red[8 + w]; }
        const float mean = S * (1.f / HH);
        const float rstd = rsqrtf(Q * (1.f / HH) - mean * mean + LN_EPS);
        float xs[4] = {xv.x, xv.y, xv.z, xv.w};
        float gs[4] = {g4.x, g4.y, g4.z, g4.w};
        float bs[4] = {b4.x, b4.y, b4.z, b4.w};
        #pragma unroll
        for (int c = 0; c < 4; c++) {
            float y = (xs[c] - mean) * rstd * gs[c] + bs[c];
            sth[t * 4 + c] = 0.5f * y * (1.f + erff(y * 0.70710678118654752f));
        }
        __syncthreads();
        #pragma unroll
        for (int li = 0; li < 3; li++) {
            const int l = wid + li * 8;
            if (l < NLB) {
                float acc = 0.f;
                #pragma unroll 8
                for (int k = lane; k < HH; k += 32)
                    acc = fmaf(sth[k], slh[l * HH + k], acc);
                #pragma unroll
                for (int o = 16; o > 0; o >>= 1) acc += __shfl_xor_sync(0xffffffffu, acc, o);
                if (lane == 0) logits[(size_t)row * NLB + l] = acc * tempv;
            }
        }
        __syncthreads();
    }
}

// ---------------- K2b: per-row max of logits ----------------
__global__ void k2b_rowmax(const float* __restrict__ logits) {
    __shared__ float sl[256 * NLB];
    const int r0 = blockIdx.x * 256;
    for (int i = threadIdx.x; i < 256 * NLB; i += 256)
        sl[i] = logits[(size_t)r0 * NLB + i];
    __syncthreads();
    float m = sl[threadIdx.x * NLB];
    #pragma unroll
    for (int l = 1; l < NLB; l++) m = fmaxf(m, sl[threadIdx.x * NLB + l]);
    g_rowmax[r0 + threadIdx.x] = m;
}

// ---------------- K3: CRF forward (exp domain, renorm /8) ----------------
__global__ void k3_crf(const float* __restrict__ logits, const int* __restrict__ labels,
                       const float* __restrict__ start_t, const float* __restrict__ end_t,
                       const float* __restrict__ trans) {
    const int b = blockIdx.x;
    const int j = threadIdx.x;  // 32 lanes
    float eT[NLB];
    #pragma unroll
    for (int i = 0; i < NLB; i++) eT[i] = (j < NLB) ? expf(trans[i * NLB + j]) : 0.f;

    const float* lg = logits + (size_t)b * LL * NLB;
    const float* rm = g_rowmax + (size_t)b * LL;
    const int* lab = labels + (size_t)b * LL;

    float a0 = (j < NLB) ? (start_t[j] + lg[j]) : -INFINITY;
    float m = a0;
    #pragma unroll
    for (int o = 16; o > 0; o >>= 1) m = fmaxf(m, __shfl_xor_sync(0xffffffffu, m, o));
    float f = expf(a0 - m);
    float logc = m;

    float e_cur = (j < NLB) ? lg[NLB + j] : -1e30f;
    float m_cur = rm[1];
    for (int t = 1; t < LL; t++) {
        float e_next = -1e30f, m_next = 0.f;
        if (t + 1 < LL) {
            if (j < NLB) e_next = lg[(size_t)(t + 1) * NLB + j];
            m_next = rm[t + 1];
        }
        float g0 = 0.f, g1 = 0.f, g2 = 0.f;
        #pragma unroll
        for (int i = 0; i < NLB; i += 3) {
            g0 = fmaf(__shfl_sync(0xffffffffu, f, i),     eT[i],     g0);
            g1 = fmaf(__shfl_sync(0xffffffffu, f, i + 1), eT[i + 1], g1);
            g2 = fmaf(__shfl_sync(0xffffffffu, f, i + 2), eT[i + 2], g2);
        }
        float fn = ((g0 + g1) + g2) * __expf(e_cur - m_cur);
        logc += m_cur;
        if ((t & 7) == 7) {
            float mx = fn;
            #pragma unroll
            for (int o = 16; o > 0; o >>= 1) mx = fmaxf(mx, __shfl_xor_sync(0xffffffffu, mx, o));
            fn = fn / mx;
            logc += logf(mx);
        }
        f = fn; e_cur = e_next; m_cur = m_next;
    }
    float sf = (j < NLB) ? f * expf(end_t[j]) : 0.f;
    #pragma unroll
    for (int o = 16; o > 0; o >>= 1) sf += __shfl_xor_sync(0xffffffffu, sf, o);
    const float logZ = logc + logf(sf);

    float sc = 0.f;
    for (int t = j; t < LL; t += 32) {
        const int lt_ = lab[t];
        sc += lg[t * NLB + lt_];
        if (t >= 1) sc += trans[lab[t - 1] * NLB + lt_];
    }
    #pragma unroll
    for (int o = 16; o > 0; o >>= 1) sc += __shfl_xor_sync(0xffffffffu, sc, o);
    if (j == 0) {
        sc += start_t[lab[0]] + end_t[lab[LL - 1]];
        g_nll[b] = logZ - sc;
    }
}

// ---------------- K4: loss ----------------
__global__ void k4_loss(float* __restrict__ out_loss) {
    float v = g_nll[threadIdx.x];
    #pragma unroll
    for (int o = 16; o > 0; o >>= 1) v += __shfl_xor_sync(0xffffffffu, v, o);
    if (threadIdx.x == 0) *out_loss = v * (1.f / BB);
}

extern "C" void kernel_launch(void* const* d_in, const int* in_sizes, int n_in,
                              void* d_out, int out_size) {
    const float* seq    = (const float*)d_in[0];
    const int*   labels = (const int*)  d_in[1];
    const float* Wtok   = (const float*)d_in[3];
    const float* gamma  = (const float*)d_in[4];
    const float* beta   = (const float*)d_in[5];
    const float* ltab   = (const float*)d_in[6];
    const float* Wlab   = (const float*)d_in[7];
    const float* temp   = (const float*)d_in[8];
    const float* startt = (const float*)d_in[9];
    const float* endt   = (const float*)d_in[10];
    const float* trans  = (const float*)d_in[11];
    float* out = (float*)d_out;

    ksplitA<<<(int)(((size_t)MM * DIN / 4) / 256), 256>>>(seq);
    ksplitB<<<dim3(DIN / 32, HH / 32), dim3(32, 8)>>>(Wtok);
    k0_labelh<<<dim3(HH / 128, NLB), 128>>>(ltab, Wlab);

    const int smem1 = NSTAGE * STAGEB;   // 184320
    cudaFuncSetAttribute(k1_mma, cudaFuncAttributeMaxDynamicSharedMemorySize, smem1);
    k1_mma<<<dim3(HH / 256, MM / 128), 512, smem1>>>();

    const int smem2 = (NLB * HH + HH + 16) * (int)sizeof(float);
    cudaFuncSetAttribute(k2_ln_gelu_logits, cudaFuncAttributeMaxDynamicSharedMemorySize, smem2);
    k2_ln_gelu_logits<<<MM / RPB, 256, smem2>>>(gamma, beta, temp, out);

    k2b_rowmax<<<MM / 256, 256>>>(out);
    k3_crf<<<BB, 32>>>(out, labels, startt, endt, trans);
    k4_loss<<<1, 32>>>(out + (out_size - 1));
}

// round 8
// speedup vs baseline: 1.3319x; 1.3319x over previous
#include <cuda_runtime.h>
#include <cuda_bf16.h>
#include <math.h>
#include <stdint.h>

#define BB   32
#define LL   1024
#define DIN  2048
#define HH   1024
#define NLB  21
#define EE   768
#define MM   (BB*LL)
#define LN_EPS 1e-5f

// ---------------- device scratch ----------------
__device__ __align__(16) float g_h[(size_t)MM * HH];
__device__ __align__(16) __nv_bfloat16 g_ahi[(size_t)MM * DIN];
__device__ __align__(16) __nv_bfloat16 g_alo[(size_t)MM * DIN];
__device__ __align__(16) __nv_bfloat16 g_bhi[(size_t)HH * DIN];   // [n][k]
__device__ __align__(16) __nv_bfloat16 g_blo[(size_t)HH * DIN];
__device__ float g_labelh[NLB * HH];
__device__ float g_rowmax[MM];
__device__ float g_nll[BB];

// ---------------- helpers ----------------
__device__ __forceinline__ uint32_t smem_u32(const void* p) {
    uint32_t a;
    asm("{ .reg .u64 t; cvta.to.shared.u64 t, %1; cvt.u32.u64 %0, t; }" : "=r"(a) : "l"(p));
    return a;
}
#define CP16(ds, sp) asm volatile("cp.async.cg.shared.global [%0], [%1], 16;" \
    :: "r"(ds), "l"(__cvta_generic_to_global(sp)) : "memory")
#define CP_COMMIT() asm volatile("cp.async.commit_group;" ::: "memory")
#define LDSM_X4(r0, r1, r2, r3, a) asm volatile( \
    "ldmatrix.sync.aligned.m8n8.x4.shared.b16 {%0,%1,%2,%3}, [%4];" \
    : "=r"(r0), "=r"(r1), "=r"(r2), "=r"(r3) : "r"(a))
#define MMA4(d, a0, a1, a2, a3, b0, b1) asm volatile( \
    "mma.sync.aligned.m16n8k16.row.col.f32.bf16.bf16.f32 " \
    "{%0,%1,%2,%3}, {%4,%5,%6,%7}, {%8,%9}, {%0,%1,%2,%3};" \
    : "+f"((d)[0]), "+f"((d)[1]), "+f"((d)[2]), "+f"((d)[3]) \
    : "r"(a0), "r"(a1), "r"(a2), "r"(a3), "r"(b0), "r"(b1))

// ---------------- split kernels ----------------
__global__ void ksplitA(const float* __restrict__ X) {
    size_t i = ((size_t)blockIdx.x * blockDim.x + threadIdx.x) * 4;
    float4 v = *(const float4*)(X + i);
    __nv_bfloat16 h0 = __float2bfloat16(v.x), h1 = __float2bfloat16(v.y);
    __nv_bfloat16 h2 = __float2bfloat16(v.z), h3 = __float2bfloat16(v.w);
    __nv_bfloat16 l0 = __float2bfloat16(v.x - __bfloat162float(h0));
    __nv_bfloat16 l1 = __float2bfloat16(v.y - __bfloat162float(h1));
    __nv_bfloat16 l2 = __float2bfloat16(v.z - __bfloat162float(h2));
    __nv_bfloat16 l3 = __float2bfloat16(v.w - __bfloat162float(h3));
    *(__nv_bfloat162*)(g_ahi + i)     = __nv_bfloat162(h0, h1);
    *(__nv_bfloat162*)(g_ahi + i + 2) = __nv_bfloat162(h2, h3);
    *(__nv_bfloat162*)(g_alo + i)     = __nv_bfloat162(l0, l1);
    *(__nv_bfloat162*)(g_alo + i + 2) = __nv_bfloat162(l2, l3);
}

__global__ void ksplitB(const float* __restrict__ W) {
    __shared__ float tile[32][33];
    const int kb = blockIdx.x * 32, nb = blockIdx.y * 32;
    const int tx = threadIdx.x, ty = threadIdx.y;  // 32 x 8
    #pragma unroll
    for (int i = 0; i < 32; i += 8)
        tile[ty + i][tx] = W[(size_t)(kb + ty + i) * HH + nb + tx];
    __syncthreads();
    #pragma unroll
    for (int i = 0; i < 32; i += 8) {
        float v = tile[tx][ty + i];   // W[kb+tx][nb+ty+i]
        __nv_bfloat16 hi = __float2bfloat16(v);
        __nv_bfloat16 lo = __float2bfloat16(v - __bfloat162float(hi));
        size_t o = (size_t)(nb + ty + i) * DIN + kb + tx;
        g_bhi[o] = hi; g_blo[o] = lo;
    }
}

// ---------------- K0: label_h ----------------
__global__ void k0_labelh(const float* __restrict__ lt, const float* __restrict__ wl) {
    const int n = blockIdx.y;
    const int h = blockIdx.x * 128 + threadIdx.x;
    float acc = 0.f;
    const float* ltr = lt + n * EE;
    #pragma unroll 4
    for (int e = 0; e < EE; e++) acc = fmaf(ltr[e], wl[(size_t)e * HH + h], acc);
    g_labelh[n * HH + h] = acc;
}

// ---------------- K1: bf16-split GEMM, 128x256 tile, 512 thr, KC=64, 2-stage ----------------
#define KC2 64
#define NCH2 (DIN / KC2)       // 32
#define TP 144                 // smem row pitch bytes (9*16B)
#define TILEA (128 * TP)       // 18432
#define TILEB2 (256 * TP)      // 36864
#define STAGEB (2 * TILEA + 2 * TILEB2)  // 110592

__device__ __forceinline__ void prefetch_chunk(uint32_t sbuf, int cRow, int cCol,
                                               int k0, int tid) {
    #pragma unroll
    for (int q = 0; q < 12; q++) {
        const int id = q * 512 + tid;
        const int c8 = id & 7;
        if (id < 2048) {             // A tiles: 128 rows x 8 xfers, hi then lo
            const int r = (id >> 3) & 127;
            const bool hi = id < 1024;
            const __nv_bfloat16* src = hi ? g_ahi : g_alo;
            const uint32_t dof = sbuf + (hi ? 0u : (uint32_t)TILEA)
                               + (uint32_t)(r * TP + c8 * 16);
            CP16(dof, src + (size_t)(cRow + r) * DIN + k0 + c8 * 8);
        } else {                     // B tiles: 256 rows x 8 xfers, hi then lo
            const int id2 = id - 2048;
            const int r = (id2 >> 3) & 255;
            const bool hi = id2 < 2048;
            const __nv_bfloat16* src = hi ? g_bhi : g_blo;
            const uint32_t dof = sbuf + 2u * TILEA + (hi ? 0u : (uint32_t)TILEB2)
                               + (uint32_t)(r * TP + c8 * 16);
            CP16(dof, src + (size_t)(cCol + r) * DIN + k0 + c8 * 8);
        }
    }
}

__global__ __launch_bounds__(512, 1) void k1_mma() {
    extern __shared__ char sm[];
    const int tid = threadIdx.x, lane = tid & 31, wid = tid >> 5;
    const int cCol = blockIdx.x * 256, cRow = blockIdx.y * 128;
    const int wm = wid >> 2, wn = wid & 3;  // warp tile 32M x 64N
    const uint32_t sb = smem_u32(sm);

    float acc[2][8][4];
    #pragma unroll
    for (int i = 0; i < 2; i++)
        #pragma unroll
        for (int j = 0; j < 8; j++)
            #pragma unroll
            for (int k = 0; k < 4; k++) acc[i][j][k] = 0.f;

    prefetch_chunk(sb, cRow, cCol, 0, tid);
    CP_COMMIT();

    const int aRow = wm * 32 + (lane & 15);            // + mt*16
    const uint32_t aKb = (uint32_t)((lane >> 4) * 16); // + ks*32
    const int bRow = wn * 64 + ((lane >> 4) & 1) * 8 + (lane & 7); // + p*16
    const uint32_t bKb = (uint32_t)(((lane >> 3) & 1) * 16);

    for (int c = 0; c < NCH2; c++) {
        if (c + 1 < NCH2) {
            prefetch_chunk(sb + (uint32_t)(((c + 1) & 1) * STAGEB), cRow, cCol,
                           (c + 1) * KC2, tid);
            CP_COMMIT();
            asm volatile("cp.async.wait_group 1;" ::: "memory");
        } else {
            asm volatile("cp.async.wait_group 0;" ::: "memory");
        }
        __syncthreads();
        const uint32_t st = sb + (uint32_t)((c & 1) * STAGEB);

        #pragma unroll
        for (int ks = 0; ks < 4; ks++) {
            uint32_t ah[2][4], al[2][4];
            #pragma unroll
            for (int mt = 0; mt < 2; mt++) {
                const uint32_t ao = st + (uint32_t)((aRow + mt * 16) * TP) + aKb + (uint32_t)(ks * 32);
                LDSM_X4(ah[mt][0], ah[mt][1], ah[mt][2], ah[mt][3], ao);
                LDSM_X4(al[mt][0], al[mt][1], al[mt][2], al[mt][3], ao + TILEA);
            }
            #pragma unroll
            for (int p = 0; p < 4; p++) {
                const uint32_t bo = st + 2u * TILEA +
                    (uint32_t)((bRow + p * 16) * TP) + bKb + (uint32_t)(ks * 32);
                uint32_t bh0, bh1, bh2, bh3, bl0, bl1, bl2, bl3;
                LDSM_X4(bh0, bh1, bh2, bh3, bo);
                LDSM_X4(bl0, bl1, bl2, bl3, bo + TILEB2);
                #pragma unroll
                for (int mt = 0; mt < 2; mt++) {
                    MMA4(acc[mt][2*p],   ah[mt][0], ah[mt][1], ah[mt][2], ah[mt][3], bh0, bh1);
                    MMA4(acc[mt][2*p],   ah[mt][0], ah[mt][1], ah[mt][2], ah[mt][3], bl0, bl1);
                    MMA4(acc[mt][2*p],   al[mt][0], al[mt][1], al[mt][2], al[mt][3], bh0, bh1);
                    MMA4(acc[mt][2*p+1], ah[mt][0], ah[mt][1], ah[mt][2], ah[mt][3], bh2, bh3);
                    MMA4(acc[mt][2*p+1], ah[mt][0], ah[mt][1], ah[mt][2], ah[mt][3], bl2, bl3);
                    MMA4(acc[mt][2*p+1], al[mt][0], al[mt][1], al[mt][2], al[mt][3], bh2, bh3);
                }
            }
        }
        __syncthreads();
    }

    #pragma unroll
    for (int mt = 0; mt < 2; mt++)
        #pragma unroll
        for (int nt = 0; nt < 8; nt++) {
            const int row = cRow + wm * 32 + mt * 16 + (lane >> 2);
            const int col = cCol + wn * 64 + nt * 8 + (lane & 3) * 2;
            float2 v0 = make_float2(acc[mt][nt][0], acc[mt][nt][1]);
            float2 v1 = make_float2(acc[mt][nt][2], acc[mt][nt][3]);
            *(float2*)&g_h[(size_t)row * HH + col] = v0;
            *(float2*)&g_h[(size_t)(row + 8) * HH + col] = v1;
        }
}

// ---------------- K2: LN + exact GELU + logits ----------------
#define RPB 16
__global__ __launch_bounds__(256)
void k2_ln_gelu_logits(const float* __restrict__ gamma, const float* __restrict__ beta,
                       const float* __restrict__ temp_p, float* __restrict__ logits) {
    extern __shared__ float smem[];
    float* slh = smem;
    float* sth = smem + NLB * HH;
    float* red = sth + HH;
    const int t = threadIdx.x, lane = t & 31, wid = t >> 5;

    for (int i = t; i < NLB * HH; i += 256) slh[i] = g_labelh[i];
    const float tempv = *temp_p;
    const float4 g4 = *(const float4*)&gamma[t * 4];
    const float4 b4 = *(const float4*)&beta[t * 4];
    __syncthreads();

    const int row0 = blockIdx.x * RPB;
    for (int r = 0; r < RPB; r++) {
        const int row = row0 + r;
        const float4 xv = *(const float4*)&g_h[(size_t)row * HH + t * 4];
        float s = xv.x + xv.y + xv.z + xv.w;
        float q = xv.x*xv.x + xv.y*xv.y + xv.z*xv.z + xv.w*xv.w;
        #pragma unroll
        for (int o = 16; o > 0; o >>= 1) {
            s += __shfl_xor_sync(0xffffffffu, s, o);
            q += __shfl_xor_sync(0xffffffffu, q, o);
        }
        if (lane == 0) { red[wid] = s; red[8 + wid] = q; }
        __syncthreads();
        float S = 0.f, Q = 0.f;
        #pragma unroll
        for (int w = 0; w < 8; w++) { S += red[w]; Q += red[8 + w]; }
        const float mean = S * (1.f / HH);
        const float rstd = rsqrtf(Q * (1.f / HH) - mean * mean + LN_EPS);
        float xs[4] = {xv.x, xv.y, xv.z, xv.w};
        float gs[4] = {g4.x, g4.y, g4.z, g4.w};
        float bs[4] = {b4.x, b4.y, b4.z, b4.w};
        #pragma unroll
        for (int c = 0; c < 4; c++) {
            float y = (xs[c] - mean) * rstd * gs[c] + bs[c];
            sth[t * 4 + c] = 0.5f * y * (1.f + erff(y * 0.70710678118654752f));
        }
        __syncthreads();
        #pragma unroll
        for (int li = 0; li < 3; li++) {
            const int l = wid + li * 8;
            if (l < NLB) {
                float acc = 0.f;
                #pragma unroll 8
                for (int k = lane; k < HH; k += 32)
                    acc = fmaf(sth[k], slh[l * HH + k], acc);
                #pragma unroll
                for (int o = 16; o > 0; o >>= 1) acc += __shfl_xor_sync(0xffffffffu, acc, o);
                if (lane == 0) logits[(size_t)row * NLB + l] = acc * tempv;
            }
        }
        __syncthreads();
    }
}

// ---------------- K2b: per-row max of logits ----------------
__global__ void k2b_rowmax(const float* __restrict__ logits) {
    __shared__ float sl[256 * NLB];
    const int r0 = blockIdx.x * 256;
    for (int i = threadIdx.x; i < 256 * NLB; i += 256)
        sl[i] = logits[(size_t)r0 * NLB + i];
    __syncthreads();
    float m = sl[threadIdx.x * NLB];
    #pragma unroll
    for (int l = 1; l < NLB; l++) m = fmaxf(m, sl[threadIdx.x * NLB + l]);
    g_rowmax[r0 + threadIdx.x] = m;
}

// ---------------- K3: CRF forward (exp domain, renorm /8) ----------------
__global__ void k3_crf(const float* __restrict__ logits, const int* __restrict__ labels,
                       const float* __restrict__ start_t, const float* __restrict__ end_t,
                       const float* __restrict__ trans) {
    const int b = blockIdx.x;
    const int j = threadIdx.x;  // 32 lanes
    float eT[NLB];
    #pragma unroll
    for (int i = 0; i < NLB; i++) eT[i] = (j < NLB) ? expf(trans[i * NLB + j]) : 0.f;

    const float* lg = logits + (size_t)b * LL * NLB;
    const float* rm = g_rowmax + (size_t)b * LL;
    const int* lab = labels + (size_t)b * LL;

    float a0 = (j < NLB) ? (start_t[j] + lg[j]) : -INFINITY;
    float m = a0;
    #pragma unroll
    for (int o = 16; o > 0; o >>= 1) m = fmaxf(m, __shfl_xor_sync(0xffffffffu, m, o));
    float f = expf(a0 - m);
    float logc = m;

    float e_cur = (j < NLB) ? lg[NLB + j] : -1e30f;
    float m_cur = rm[1];
    for (int t = 1; t < LL; t++) {
        float e_next = -1e30f, m_next = 0.f;
        if (t + 1 < LL) {
            if (j < NLB) e_next = lg[(size_t)(t + 1) * NLB + j];
            m_next = rm[t + 1];
        }
        float g0 = 0.f, g1 = 0.f, g2 = 0.f;
        #pragma unroll
        for (int i = 0; i < NLB; i += 3) {
            g0 = fmaf(__shfl_sync(0xffffffffu, f, i),     eT[i],     g0);
            g1 = fmaf(__shfl_sync(0xffffffffu, f, i + 1), eT[i + 1], g1);
            g2 = fmaf(__shfl_sync(0xffffffffu, f, i + 2), eT[i + 2], g2);
        }
        float fn = ((g0 + g1) + g2) * __expf(e_cur - m_cur);
        logc += m_cur;
        if ((t & 7) == 7) {
            float mx = fn;
            #pragma unroll
            for (int o = 16; o > 0; o >>= 1) mx = fmaxf(mx, __shfl_xor_sync(0xffffffffu, mx, o));
            fn = fn / mx;
            logc += logf(mx);
        }
        f = fn; e_cur = e_next; m_cur = m_next;
    }
    float sf = (j < NLB) ? f * expf(end_t[j]) : 0.f;
    #pragma unroll
    for (int o = 16; o > 0; o >>= 1) sf += __shfl_xor_sync(0xffffffffu, sf, o);
    const float logZ = logc + logf(sf);

    float sc = 0.f;
    for (int t = j; t < LL; t += 32) {
        const int lt_ = lab[t];
        sc += lg[t * NLB + lt_];
        if (t >= 1) sc += trans[lab[t - 1] * NLB + lt_];
    }
    #pragma unroll
    for (int o = 16; o > 0; o >>= 1) sc += __shfl_xor_sync(0xffffffffu, sc, o);
    if (j == 0) {
        sc += start_t[lab[0]] + end_t[lab[LL - 1]];
        g_nll[b] = logZ - sc;
    }
}

// ---------------- K4: loss ----------------
__global__ void k4_loss(float* __restrict__ out_loss) {
    float v = g_nll[threadIdx.x];
    #pragma unroll
    for (int o = 16; o > 0; o >>= 1) v += __shfl_xor_sync(0xffffffffu, v, o);
    if (threadIdx.x == 0) *out_loss = v * (1.f / BB);
}

extern "C" void kernel_launch(void* const* d_in, const int* in_sizes, int n_in,
                              void* d_out, int out_size) {
    const float* seq    = (const float*)d_in[0];
    const int*   labels = (const int*)  d_in[1];
    const float* Wtok   = (const float*)d_in[3];
    const float* gamma  = (const float*)d_in[4];
    const float* beta   = (const float*)d_in[5];
    const float* ltab   = (const float*)d_in[6];
    const float* Wlab   = (const float*)d_in[7];
    const float* temp   = (const float*)d_in[8];
    const float* startt = (const float*)d_in[9];
    const float* endt   = (const float*)d_in[10];
    const float* trans  = (const float*)d_in[11];
    float* out = (float*)d_out;

    ksplitA<<<(int)(((size_t)MM * DIN / 4) / 256), 256>>>(seq);
    ksplitB<<<dim3(DIN / 32, HH / 32), dim3(32, 8)>>>(Wtok);
    k0_labelh<<<dim3(HH / 128, NLB), 128>>>(ltab, Wlab);

    const int smem1 = 2 * STAGEB;   // 221184
    cudaFuncSetAttribute(k1_mma, cudaFuncAttributeMaxDynamicSharedMemorySize, smem1);
    k1_mma<<<dim3(HH / 256, MM / 128), 512, smem1>>>();

    const int smem2 = (NLB * HH + HH + 16) * (int)sizeof(float);
    cudaFuncSetAttribute(k2_ln_gelu_logits, cudaFuncAttributeMaxDynamicSharedMemorySize, smem2);
    k2_ln_gelu_logits<<<MM / RPB, 256, smem2>>>(gamma, beta, temp, out);

    k2b_rowmax<<<MM / 256, 256>>>(out);
    k3_crf<<<BB, 32>>>(out, labels, startt, endt, trans);
    k4_loss<<<1, 32>>>(out + (out_size - 1));
}

// round 9
// speedup vs baseline: 1.7083x; 1.2826x over previous
#include <cuda_runtime.h>
#include <cuda_bf16.h>
#include <math.h>
#include <stdint.h>

#define BB   32
#define LL   1024
#define DIN  2048
#define HH   1024
#define NLB  21
#define EE   768
#define MM   (BB*LL)
#define LN_EPS 1e-5f

// ---------------- device scratch ----------------
__device__ __align__(16) float g_h[(size_t)MM * HH];
__device__ __align__(16) __nv_bfloat16 g_ahi[(size_t)MM * DIN];
__device__ __align__(16) __nv_bfloat16 g_alo[(size_t)MM * DIN];
__device__ __align__(16) __nv_bfloat16 g_bhi[(size_t)HH * DIN];   // [n][k]
__device__ __align__(16) __nv_bfloat16 g_blo[(size_t)HH * DIN];
__device__ __align__(16) float g_labelh[NLB * HH];
__device__ __align__(16) float g_rowmax[MM];
__device__ float g_nll[BB];

// ---------------- helpers ----------------
__device__ __forceinline__ uint32_t smem_u32(const void* p) {
    uint32_t a;
    asm("{ .reg .u64 t; cvta.to.shared.u64 t, %1; cvt.u32.u64 %0, t; }" : "=r"(a) : "l"(p));
    return a;
}
#define CP16(ds, sp) asm volatile("cp.async.cg.shared.global [%0], [%1], 16;" \
    :: "r"(ds), "l"(__cvta_generic_to_global(sp)) : "memory")
#define CP_COMMIT() asm volatile("cp.async.commit_group;" ::: "memory")
#define LDSM_X4(r0, r1, r2, r3, a) asm volatile( \
    "ldmatrix.sync.aligned.m8n8.x4.shared.b16 {%0,%1,%2,%3}, [%4];" \
    : "=r"(r0), "=r"(r1), "=r"(r2), "=r"(r3) : "r"(a))
#define MMA4(d, a0, a1, a2, a3, b0, b1) asm volatile( \
    "mma.sync.aligned.m16n8k16.row.col.f32.bf16.bf16.f32 " \
    "{%0,%1,%2,%3}, {%4,%5,%6,%7}, {%8,%9}, {%0,%1,%2,%3};" \
    : "+f"((d)[0]), "+f"((d)[1]), "+f"((d)[2]), "+f"((d)[3]) \
    : "r"(a0), "r"(a1), "r"(a2), "r"(a3), "r"(b0), "r"(b1))

// ---------------- split kernels ----------------
__global__ void ksplitA(const float* __restrict__ X) {
    size_t i = ((size_t)blockIdx.x * blockDim.x + threadIdx.x) * 4;
    float4 v = *(const float4*)(X + i);
    __nv_bfloat16 h0 = __float2bfloat16(v.x), h1 = __float2bfloat16(v.y);
    __nv_bfloat16 h2 = __float2bfloat16(v.z), h3 = __float2bfloat16(v.w);
    __nv_bfloat16 l0 = __float2bfloat16(v.x - __bfloat162float(h0));
    __nv_bfloat16 l1 = __float2bfloat16(v.y - __bfloat162float(h1));
    __nv_bfloat16 l2 = __float2bfloat16(v.z - __bfloat162float(h2));
    __nv_bfloat16 l3 = __float2bfloat16(v.w - __bfloat162float(h3));
    *(__nv_bfloat162*)(g_ahi + i)     = __nv_bfloat162(h0, h1);
    *(__nv_bfloat162*)(g_ahi + i + 2) = __nv_bfloat162(h2, h3);
    *(__nv_bfloat162*)(g_alo + i)     = __nv_bfloat162(l0, l1);
    *(__nv_bfloat162*)(g_alo + i + 2) = __nv_bfloat162(l2, l3);
}

__global__ void ksplitB(const float* __restrict__ W) {
    __shared__ float tile[32][33];
    const int kb = blockIdx.x * 32, nb = blockIdx.y * 32;
    const int tx = threadIdx.x, ty = threadIdx.y;  // 32 x 8
    #pragma unroll
    for (int i = 0; i < 32; i += 8)
        tile[ty + i][tx] = W[(size_t)(kb + ty + i) * HH + nb + tx];
    __syncthreads();
    #pragma unroll
    for (int i = 0; i < 32; i += 8) {
        float v = tile[tx][ty + i];   // W[kb+tx][nb+ty+i]
        __nv_bfloat16 hi = __float2bfloat16(v);
        __nv_bfloat16 lo = __float2bfloat16(v - __bfloat162float(hi));
        size_t o = (size_t)(nb + ty + i) * DIN + kb + tx;
        g_bhi[o] = hi; g_blo[o] = lo;
    }
}

// ---------------- K0: label_h ----------------
__global__ void k0_labelh(const float* __restrict__ lt, const float* __restrict__ wl) {
    const int n = blockIdx.y;
    const int h = blockIdx.x * 128 + threadIdx.x;
    float acc = 0.f;
    const float* ltr = lt + n * EE;
    #pragma unroll 4
    for (int e = 0; e < EE; e++) acc = fmaf(ltr[e], wl[(size_t)e * HH + h], acc);
    g_labelh[n * HH + h] = acc;
}

// ---------------- K1: bf16-split GEMM, 128x256 tile, 512 thr, KC=64, 2-stage ----------------
#define KC2 64
#define NCH2 (DIN / KC2)       // 32
#define TP 144                 // smem row pitch bytes (9*16B)
#define TILEA (128 * TP)       // 18432
#define TILEB2 (256 * TP)      // 36864
#define STAGEB (2 * TILEA + 2 * TILEB2)  // 110592

__device__ __forceinline__ void prefetch_chunk(uint32_t sbuf, int cRow, int cCol,
                                               int k0, int tid) {
    #pragma unroll
    for (int q = 0; q < 12; q++) {
        const int id = q * 512 + tid;
        const int c8 = id & 7;
        if (id < 2048) {             // A tiles: 128 rows x 8 xfers, hi then lo
            const int r = (id >> 3) & 127;
            const bool hi = id < 1024;
            const __nv_bfloat16* src = hi ? g_ahi : g_alo;
            const uint32_t dof = sbuf + (hi ? 0u : (uint32_t)TILEA)
                               + (uint32_t)(r * TP + c8 * 16);
            CP16(dof, src + (size_t)(cRow + r) * DIN + k0 + c8 * 8);
        } else {                     // B tiles: 256 rows x 8 xfers, hi then lo
            const int id2 = id - 2048;
            const int r = (id2 >> 3) & 255;
            const bool hi = id2 < 2048;
            const __nv_bfloat16* src = hi ? g_bhi : g_blo;
            const uint32_t dof = sbuf + 2u * TILEA + (hi ? 0u : (uint32_t)TILEB2)
                               + (uint32_t)(r * TP + c8 * 16);
            CP16(dof, src + (size_t)(cCol + r) * DIN + k0 + c8 * 8);
        }
    }
}

__global__ __launch_bounds__(512, 1) void k1_mma() {
    extern __shared__ char sm[];
    const int tid = threadIdx.x, lane = tid & 31, wid = tid >> 5;
    const int cCol = blockIdx.x * 256, cRow = blockIdx.y * 128;
    const int wm = wid >> 2, wn = wid & 3;  // warp tile 32M x 64N
    const uint32_t sb = smem_u32(sm);

    float acc[2][8][4];
    #pragma unroll
    for (int i = 0; i < 2; i++)
        #pragma unroll
        for (int j = 0; j < 8; j++)
            #pragma unroll
            for (int k = 0; k < 4; k++) acc[i][j][k] = 0.f;

    prefetch_chunk(sb, cRow, cCol, 0, tid);
    CP_COMMIT();

    const int aRow = wm * 32 + (lane & 15);            // + mt*16
    const uint32_t aKb = (uint32_t)((lane >> 4) * 16); // + ks*32
    const int bRow = wn * 64 + ((lane >> 4) & 1) * 8 + (lane & 7); // + p*16
    const uint32_t bKb = (uint32_t)(((lane >> 3) & 1) * 16);

    for (int c = 0; c < NCH2; c++) {
        if (c + 1 < NCH2) {
            prefetch_chunk(sb + (uint32_t)(((c + 1) & 1) * STAGEB), cRow, cCol,
                           (c + 1) * KC2, tid);
            CP_COMMIT();
            asm volatile("cp.async.wait_group 1;" ::: "memory");
        } else {
            asm volatile("cp.async.wait_group 0;" ::: "memory");
        }
        __syncthreads();
        const uint32_t st = sb + (uint32_t)((c & 1) * STAGEB);

        #pragma unroll
        for (int ks = 0; ks < 4; ks++) {
            uint32_t ah[2][4], al[2][4];
            #pragma unroll
            for (int mt = 0; mt < 2; mt++) {
                const uint32_t ao = st + (uint32_t)((aRow + mt * 16) * TP) + aKb + (uint32_t)(ks * 32);
                LDSM_X4(ah[mt][0], ah[mt][1], ah[mt][2], ah[mt][3], ao);
                LDSM_X4(al[mt][0], al[mt][1], al[mt][2], al[mt][3], ao + TILEA);
            }
            #pragma unroll
            for (int p = 0; p < 4; p++) {
                const uint32_t bo = st + 2u * TILEA +
                    (uint32_t)((bRow + p * 16) * TP) + bKb + (uint32_t)(ks * 32);
                uint32_t bh0, bh1, bh2, bh3, bl0, bl1, bl2, bl3;
                LDSM_X4(bh0, bh1, bh2, bh3, bo);
                LDSM_X4(bl0, bl1, bl2, bl3, bo + TILEB2);
                #pragma unroll
                for (int mt = 0; mt < 2; mt++) {
                    MMA4(acc[mt][2*p],   ah[mt][0], ah[mt][1], ah[mt][2], ah[mt][3], bh0, bh1);
                    MMA4(acc[mt][2*p],   ah[mt][0], ah[mt][1], ah[mt][2], ah[mt][3], bl0, bl1);
                    MMA4(acc[mt][2*p],   al[mt][0], al[mt][1], al[mt][2], al[mt][3], bh0, bh1);
                    MMA4(acc[mt][2*p+1], ah[mt][0], ah[mt][1], ah[mt][2], ah[mt][3], bh2, bh3);
                    MMA4(acc[mt][2*p+1], ah[mt][0], ah[mt][1], ah[mt][2], ah[mt][3], bl2, bl3);
                    MMA4(acc[mt][2*p+1], al[mt][0], al[mt][1], al[mt][2], al[mt][3], bh2, bh3);
                }
            }
        }
        __syncthreads();
    }

    #pragma unroll
    for (int mt = 0; mt < 2; mt++)
        #pragma unroll
        for (int nt = 0; nt < 8; nt++) {
            const int row = cRow + wm * 32 + mt * 16 + (lane >> 2);
            const int col = cCol + wn * 64 + nt * 8 + (lane & 3) * 2;
            float2 v0 = make_float2(acc[mt][nt][0], acc[mt][nt][1]);
            float2 v1 = make_float2(acc[mt][nt][2], acc[mt][nt][3]);
            *(float2*)&g_h[(size_t)row * HH + col] = v0;
            *(float2*)&g_h[(size_t)(row + 8) * HH + col] = v1;
        }
}

// ---------------- K2: warp-per-row LN + exact GELU + logits + rowmax ----------------
__global__ __launch_bounds__(256)
void k2_fused(const float* __restrict__ gamma, const float* __restrict__ beta,
              const float* __restrict__ temp_p, float* __restrict__ logits) {
    extern __shared__ float slh[];   // NLB*HH floats
    const int tid = threadIdx.x, lane = tid & 31, wid = tid >> 5;

    const float4* lh4 = (const float4*)g_labelh;
    float4* slh4 = (float4*)slh;
    #pragma unroll
    for (int i = tid; i < NLB * HH / 4; i += 256) slh4[i] = lh4[i];
    const float tempv = *temp_p;
    const float4* gamma4 = (const float4*)gamma;
    const float4* beta4  = (const float4*)beta;
    __syncthreads();

    const int rowbase = blockIdx.x * 64 + wid * 8;
    for (int r = 0; r < 8; r++) {
        const int row = rowbase + r;
        const float4* hr4 = (const float4*)(g_h + (size_t)row * HH);
        float4 xv[8];
        #pragma unroll
        for (int q = 0; q < 8; q++) xv[q] = hr4[lane + 32 * q];

        float s = 0.f, ss = 0.f;
        #pragma unroll
        for (int q = 0; q < 8; q++) {
            s  += xv[q].x + xv[q].y + xv[q].z + xv[q].w;
            ss += xv[q].x*xv[q].x + xv[q].y*xv[q].y + xv[q].z*xv[q].z + xv[q].w*xv[q].w;
        }
        #pragma unroll
        for (int o = 16; o > 0; o >>= 1) {
            s  += __shfl_xor_sync(0xffffffffu, s, o);
            ss += __shfl_xor_sync(0xffffffffu, ss, o);
        }
        const float mean = s * (1.f / HH);
        const float rstd = rsqrtf(ss * (1.f / HH) - mean * mean + LN_EPS);

        float acc[NLB];
        #pragma unroll
        for (int l = 0; l < NLB; l++) acc[l] = 0.f;

        #pragma unroll
        for (int q = 0; q < 8; q++) {
            const float4 g4 = gamma4[lane + 32 * q];
            const float4 b4 = beta4[lane + 32 * q];
            float y0 = (xv[q].x - mean) * rstd * g4.x + b4.x;
            float y1 = (xv[q].y - mean) * rstd * g4.y + b4.y;
            float y2 = (xv[q].z - mean) * rstd * g4.z + b4.z;
            float y3 = (xv[q].w - mean) * rstd * g4.w + b4.w;
            const float t0 = 0.5f * y0 * (1.f + erff(y0 * 0.70710678118654752f));
            const float t1 = 0.5f * y1 * (1.f + erff(y1 * 0.70710678118654752f));
            const float t2 = 0.5f * y2 * (1.f + erff(y2 * 0.70710678118654752f));
            const float t3 = 0.5f * y3 * (1.f + erff(y3 * 0.70710678118654752f));
            #pragma unroll
            for (int l = 0; l < NLB; l++) {
                const float4 w4 = slh4[l * 256 + lane + 32 * q];
                acc[l] = fmaf(t0, w4.x, fmaf(t1, w4.y, fmaf(t2, w4.z, fmaf(t3, w4.w, acc[l]))));
            }
        }

        float out = 0.f;
        #pragma unroll
        for (int l = 0; l < NLB; l++) {
            float v = acc[l];
            #pragma unroll
            for (int o = 16; o > 0; o >>= 1) v += __shfl_xor_sync(0xffffffffu, v, o);
            if (lane == l) out = v * tempv;
        }
        if (lane < NLB) logits[(size_t)row * NLB + lane] = out;
        float mv = (lane < NLB) ? out : -INFINITY;
        #pragma unroll
        for (int o = 16; o > 0; o >>= 1) mv = fmaxf(mv, __shfl_xor_sync(0xffffffffu, mv, o));
        if (lane == 0) g_rowmax[row] = mv;
    }
}

// ---------------- K3: CRF forward, cp.async-staged, exp domain, renorm /8 ----------------
#define CRF_CH 32                       // steps per chunk
#define CRF_NC (LL / CRF_CH)            // 32 chunks
#define CRF_FB (CRF_CH * NLB)           // 672 logits floats per chunk
#define CRF_BF (CRF_FB + CRF_CH)        // +32 rowmax = 704 floats

__global__ void k3_crf(const float* __restrict__ logits, const int* __restrict__ labels,
                       const float* __restrict__ start_t, const float* __restrict__ end_t,
                       const float* __restrict__ trans) {
    __shared__ __align__(16) float sbuf[3][CRF_BF];
    const int b = blockIdx.x;
    const int j = threadIdx.x;  // 32 lanes
    float eT[NLB];
    #pragma unroll
    for (int i = 0; i < NLB; i++) eT[i] = (j < NLB) ? expf(trans[i * NLB + j]) : 0.f;

    const float* lg = logits + (size_t)b * LL * NLB;
    const float* rm = g_rowmax + (size_t)b * LL;
    const int* lab = labels + (size_t)b * LL;

    const char* lgB = (const char*)lg;
    const char* rmB = (const char*)rm;

    // stage chunk 0 and 1
    #pragma unroll
    for (int cc = 0; cc < 2; cc++) {
        const uint32_t dst = smem_u32(&sbuf[cc][0]);
        for (int u = j; u < 176; u += 32) {
            const char* src = (u < 168) ? (lgB + cc * 2688 + u * 16)
                                        : (rmB + cc * 128 + (u - 168) * 16);
            CP16(dst + u * 16, src);
        }
        CP_COMMIT();
    }

    float f = 0.f, logc = 0.f;

    for (int c = 0; c < CRF_NC; c++) {
        if (c + 2 < CRF_NC) {
            const int nc = c + 2;
            const uint32_t dst = smem_u32(&sbuf[nc % 3][0]);
            for (int u = j; u < 176; u += 32) {
                const char* src = (u < 168) ? (lgB + nc * 2688 + u * 16)
                                            : (rmB + nc * 128 + (u - 168) * 16);
                CP16(dst + u * 16, src);
            }
            CP_COMMIT();
            asm volatile("cp.async.wait_group 2;" ::: "memory");
        } else if (c + 1 < CRF_NC) {
            asm volatile("cp.async.wait_group 1;" ::: "memory");
        } else {
            asm volatile("cp.async.wait_group 0;" ::: "memory");
        }
        __syncwarp();
        const float* sc = sbuf[c % 3];

        int w0 = 0;
        if (c == 0) {
            // init at t=0
            float a0 = (j < NLB) ? (start_t[j] + sc[j]) : -INFINITY;
            float m = a0;
            #pragma unroll
            for (int o = 16; o > 0; o >>= 1) m = fmaxf(m, __shfl_xor_sync(0xffffffffu, m, o));
            f = expf(a0 - m);
            logc = m;
            w0 = 1;
        }

        #pragma unroll 4
        for (int w = w0; w < CRF_CH; w++) {
            const int t = c * CRF_CH + w;
            const float e = (j < NLB) ? sc[w * NLB + j] : -1e30f;
            const float mt = sc[CRF_FB + w];
            float g0 = 0.f, g1 = 0.f, g2 = 0.f;
            #pragma unroll
            for (int i = 0; i < NLB; i += 3) {
                g0 = fmaf(__shfl_sync(0xffffffffu, f, i),     eT[i],     g0);
                g1 = fmaf(__shfl_sync(0xffffffffu, f, i + 1), eT[i + 1], g1);
                g2 = fmaf(__shfl_sync(0xffffffffu, f, i + 2), eT[i + 2], g2);
            }
            float fn = ((g0 + g1) + g2) * __expf(e - mt);
            logc += mt;
            if ((t & 7) == 7) {
                float mx = fn;
                #pragma unroll
                for (int o = 16; o > 0; o >>= 1) mx = fmaxf(mx, __shfl_xor_sync(0xffffffffu, mx, o));
                fn = fn / mx;
                logc += logf(mx);
            }
            f = fn;
        }
        __syncwarp();
    }

    float sf = (j < NLB) ? f * expf(end_t[j]) : 0.f;
    #pragma unroll
    for (int o = 16; o > 0; o >>= 1) sf += __shfl_xor_sync(0xffffffffu, sf, o);
    const float logZ = logc + logf(sf);

    float sc2 = 0.f;
    for (int t = j; t < LL; t += 32) {
        const int lt_ = lab[t];
        sc2 += lg[t * NLB + lt_];
        if (t >= 1) sc2 += trans[lab[t - 1] * NLB + lt_];
    }
    #pragma unroll
    for (int o = 16; o > 0; o >>= 1) sc2 += __shfl_xor_sync(0xffffffffu, sc2, o);
    if (j == 0) {
        sc2 += start_t[lab[0]] + end_t[lab[LL - 1]];
        g_nll[b] = logZ - sc2;
    }
}

// ---------------- K4: loss ----------------
__global__ void k4_loss(float* __restrict__ out_loss) {
    float v = g_nll[threadIdx.x];
    #pragma unroll
    for (int o = 16; o > 0; o >>= 1) v += __shfl_xor_sync(0xffffffffu, v, o);
    if (threadIdx.x == 0) *out_loss = v * (1.f / BB);
}

extern "C" void kernel_launch(void* const* d_in, const int* in_sizes, int n_in,
                              void* d_out, int out_size) {
    const float* seq    = (const float*)d_in[0];
    const int*   labels = (const int*)  d_in[1];
    const float* Wtok   = (const float*)d_in[3];
    const float* gamma  = (const float*)d_in[4];
    const float* beta   = (const float*)d_in[5];
    const float* ltab   = (const float*)d_in[6];
    const float* Wlab   = (const float*)d_in[7];
    const float* temp   = (const float*)d_in[8];
    const float* startt = (const float*)d_in[9];
    const float* endt   = (const float*)d_in[10];
    const float* trans  = (const float*)d_in[11];
    float* out = (float*)d_out;

    ksplitA<<<(int)(((size_t)MM * DIN / 4) / 256), 256>>>(seq);
    ksplitB<<<dim3(DIN / 32, HH / 32), dim3(32, 8)>>>(Wtok);
    k0_labelh<<<dim3(HH / 128, NLB), 128>>>(ltab, Wlab);

    const int smem1 = 2 * STAGEB;   // 221184
    cudaFuncSetAttribute(k1_mma, cudaFuncAttributeMaxDynamicSharedMemorySize, smem1);
    k1_mma<<<dim3(HH / 256, MM / 128), 512, smem1>>>();

    const int smem2 = NLB * HH * (int)sizeof(float);   // 86016
    cudaFuncSetAttribute(k2_fused, cudaFuncAttributeMaxDynamicSharedMemorySize, smem2);
    k2_fused<<<MM / 64, 256, smem2>>>(gamma, beta, temp, out);

    k3_crf<<<BB, 32>>>(out, labels, startt, endt, trans);
    k4_loss<<<1, 32>>>(out + (out_size - 1));
}